// round 12
// baseline (speedup 1.0000x reference)
#include <cuda_runtime.h>
#include <cuda_bf16.h>
#include <cstdint>
#include <cstddef>

// ---------------------------------------------------------------------------
// DeepseekV3MoE on GB300 (sm_103 ptxas target: tcgen05 unavailable -> mma.sync).
// Router is a mathematical no-op (comb_w == 1 exactly):
//   out = swiglu_mlp(x; sh_*) + swiglu_mlp(x; r_*)
// 3xBF16 split GEMMs (hi*hi + hi*lo + lo*hi), fp32 accumulate, rel_err ~4e-5.
// This round: 3-stage cp.async pipeline w/ single barrier per K-step,
// gate+up fused into one GEMM (N doubled), launch order arranged so ncu
// (-s 5 -c 1) profiles the big shared up-projection GEMM.
// ---------------------------------------------------------------------------

#define HIDDEN    2048
#define INTER     8192
#define MOE_INTER 1024
#define TOKENS    (4 * 2048)

#define BM 128
#define BN 128
#define BK 32
#define LDA 40                 // BK + 8 pad: conflict-free ldmatrix
#define TILE_ELEMS (BM * LDA)
#define NSTAGE 3
#define SMEM_BYTES (NSTAGE * 4 * TILE_ELEMS * 2)   // 122880

// ------------------------------ scratch (device globals) -------------------
__device__ __align__(256) __nv_bfloat16 g_XH[TOKENS * HIDDEN];
__device__ __align__(256) __nv_bfloat16 g_XL[TOKENS * HIDDEN];

// gate+up fused weight splits: rows [0,INTER) = gate, [INTER,2*INTER) = up
__device__ __align__(256) __nv_bfloat16 g_SHGU_H[2 * INTER * HIDDEN];
__device__ __align__(256) __nv_bfloat16 g_SHGU_L[2 * INTER * HIDDEN];
__device__ __align__(256) __nv_bfloat16 g_SHD_H[HIDDEN * INTER];
__device__ __align__(256) __nv_bfloat16 g_SHD_L[HIDDEN * INTER];

__device__ __align__(256) __nv_bfloat16 g_RGU_H[2 * MOE_INTER * HIDDEN];
__device__ __align__(256) __nv_bfloat16 g_RGU_L[2 * MOE_INTER * HIDDEN];
__device__ __align__(256) __nv_bfloat16 g_RD_H[HIDDEN * MOE_INTER];
__device__ __align__(256) __nv_bfloat16 g_RD_L[HIDDEN * MOE_INTER];

__device__ __align__(256) float g_GU[(size_t)TOKENS * 2 * INTER];    // 512MB
__device__ __align__(256) __nv_bfloat16 g_HSH_H[(size_t)TOKENS * INTER];
__device__ __align__(256) __nv_bfloat16 g_HSH_L[(size_t)TOKENS * INTER];

__device__ __align__(256) float g_GUR[(size_t)TOKENS * 2 * MOE_INTER];
__device__ __align__(256) __nv_bfloat16 g_HR_H[(size_t)TOKENS * MOE_INTER];
__device__ __align__(256) __nv_bfloat16 g_HR_L[(size_t)TOKENS * MOE_INTER];

// ------------------------------ device helpers -----------------------------
__device__ __forceinline__ uint32_t smem_u32(const void* p) {
    return (uint32_t)__cvta_generic_to_shared(p);
}
__device__ __forceinline__ void ldsm_x4(uint32_t r[4], uint32_t addr) {
    asm volatile("ldmatrix.sync.aligned.m8n8.x4.shared.b16 {%0,%1,%2,%3}, [%4];"
                 : "=r"(r[0]), "=r"(r[1]), "=r"(r[2]), "=r"(r[3]) : "r"(addr));
}
__device__ __forceinline__ void mma_bf16(float c[4], const uint32_t a[4], const uint32_t b[2]) {
    asm volatile(
        "mma.sync.aligned.m16n8k16.row.col.f32.bf16.bf16.f32 "
        "{%0,%1,%2,%3}, {%4,%5,%6,%7}, {%8,%9}, {%0,%1,%2,%3};"
        : "+f"(c[0]), "+f"(c[1]), "+f"(c[2]), "+f"(c[3])
        : "r"(a[0]), "r"(a[1]), "r"(a[2]), "r"(a[3]), "r"(b[0]), "r"(b[1]));
}
#define CP_ASYNC16(dst, src) \
    asm volatile("cp.async.cg.shared.global [%0], [%1], 16;" :: "r"(dst), "l"(src))
#define CP_COMMIT() asm volatile("cp.async.commit_group;")
#define CP_WAIT1()  asm volatile("cp.async.wait_group 1;")

// ------------------------------ split helpers ------------------------------
__device__ __forceinline__ void split4(float4 v, __nv_bfloat162* hp, __nv_bfloat162* lp,
                                       size_t i2) {
    __nv_bfloat16 h0 = __float2bfloat16(v.x);
    __nv_bfloat16 h1 = __float2bfloat16(v.y);
    __nv_bfloat16 h2 = __float2bfloat16(v.z);
    __nv_bfloat16 h3 = __float2bfloat16(v.w);
    __nv_bfloat16 l0 = __float2bfloat16(v.x - __bfloat162float(h0));
    __nv_bfloat16 l1 = __float2bfloat16(v.y - __bfloat162float(h1));
    __nv_bfloat16 l2 = __float2bfloat16(v.z - __bfloat162float(h2));
    __nv_bfloat16 l3 = __float2bfloat16(v.w - __bfloat162float(h3));
    hp[i2]     = __nv_bfloat162(h0, h1);
    hp[i2 + 1] = __nv_bfloat162(h2, h3);
    lp[i2]     = __nv_bfloat162(l0, l1);
    lp[i2 + 1] = __nv_bfloat162(l2, l3);
}

// one kernel splits all six weight tensors (keeps launch count down and
// puts the big GEMM at ncu's capture index)
#define W1 ((size_t)INTER * HIDDEN / 4)        // f4 per big weight
#define R1 ((size_t)MOE_INTER * HIDDEN / 4)    // f4 per routed weight
__global__ void split_weights_kernel(
    const float* __restrict__ shg, const float* __restrict__ shu,
    const float* __restrict__ shd, const float* __restrict__ rg,
    const float* __restrict__ ru,  const float* __restrict__ rd,
    __nv_bfloat16* __restrict__ SHGU_H, __nv_bfloat16* __restrict__ SHGU_L,
    __nv_bfloat16* __restrict__ SHD_H,  __nv_bfloat16* __restrict__ SHD_L,
    __nv_bfloat16* __restrict__ RGU_H,  __nv_bfloat16* __restrict__ RGU_L,
    __nv_bfloat16* __restrict__ RD_H,   __nv_bfloat16* __restrict__ RD_L) {
    size_t i = (size_t)blockIdx.x * blockDim.x + threadIdx.x;
    const size_t total = 3 * W1 + 3 * R1;
    if (i >= total) return;
    const float* src; __nv_bfloat16* hi; __nv_bfloat16* lo; size_t off;
    if (i < W1)               { src = shg; hi = SHGU_H; lo = SHGU_L; off = i; }
    else if (i < 2 * W1)      { src = shu; hi = SHGU_H; lo = SHGU_L; off = i; src -= W1 * 4 / 1, src = shu; off = i; }
    else if (i < 3 * W1)      { src = shd; hi = SHD_H;  lo = SHD_L;  off = i - 2 * W1; }
    else if (i < 3 * W1 + R1) { src = rg;  hi = RGU_H;  lo = RGU_L;  off = i - 3 * W1; }
    else if (i < 3 * W1 + 2 * R1) { src = ru; hi = RGU_H; lo = RGU_L; off = i - 3 * W1; }
    else                      { src = rd;  hi = RD_H;   lo = RD_L;   off = i - 3 * W1 - 2 * R1; }
    // fix source index for the concatenated cases
    size_t sidx;
    if (i < W1)                    sidx = i;
    else if (i < 2 * W1)           sidx = i - W1;            // shu -> second half of SHGU
    else if (i < 3 * W1)           sidx = off;
    else if (i < 3 * W1 + R1)      sidx = off;
    else if (i < 3 * W1 + 2 * R1)  sidx = i - (3 * W1 + R1); // ru -> second half of RGU
    else                           sidx = off;
    float4 v = reinterpret_cast<const float4*>(src)[sidx];
    split4(v, reinterpret_cast<__nv_bfloat162*>(hi),
              reinterpret_cast<__nv_bfloat162*>(lo), 2 * off);
}

__global__ void split_x_kernel(const float* __restrict__ src,
                               __nv_bfloat16* __restrict__ hi,
                               __nv_bfloat16* __restrict__ lo, int n4) {
    int i = blockIdx.x * blockDim.x + threadIdx.x;
    if (i >= n4) return;
    float4 v = reinterpret_cast<const float4*>(src)[i];
    split4(v, reinterpret_cast<__nv_bfloat162*>(hi),
              reinterpret_cast<__nv_bfloat162*>(lo), 2 * (size_t)i);
}

// swiglu over fused C[T, 2*I] (gate cols [0,I), up cols [I,2I)) -> hi/lo [T, I]
__global__ void swiglu_split_kernel(const float* __restrict__ C,
                                    __nv_bfloat16* __restrict__ hi,
                                    __nv_bfloat16* __restrict__ lo,
                                    int I4, int n4) {
    int i = blockIdx.x * blockDim.x + threadIdx.x;
    if (i >= n4) return;
    int t = i / I4, r = i % I4;
    const float4* gp = reinterpret_cast<const float4*>(C + (size_t)t * 2 * (I4 * 4)) + r;
    float4 gv = gp[0];
    float4 uv = gp[I4];
    float h[4];
    h[0] = gv.x * (1.0f / (1.0f + expf(-gv.x))) * uv.x;
    h[1] = gv.y * (1.0f / (1.0f + expf(-gv.y))) * uv.y;
    h[2] = gv.z * (1.0f / (1.0f + expf(-gv.z))) * uv.z;
    h[3] = gv.w * (1.0f / (1.0f + expf(-gv.w))) * uv.w;
    float4 hv = make_float4(h[0], h[1], h[2], h[3]);
    split4(hv, reinterpret_cast<__nv_bfloat162*>(hi),
               reinterpret_cast<__nv_bfloat162*>(lo), 2 * (size_t)i);
}

// ------------------------------ 3xBF16 GEMM ---------------------------------
// C[M,N] = A[M,K] @ B[N,K]^T; 3-stage cp.async pipeline, one barrier/K-step.
__global__ void __launch_bounds__(256, 1)
gemm3x_kernel(const __nv_bfloat16* __restrict__ Ah, const __nv_bfloat16* __restrict__ Al,
              const __nv_bfloat16* __restrict__ Bh, const __nv_bfloat16* __restrict__ Bl,
              float* __restrict__ C, int M, int N, int K, int accumulate) {
    extern __shared__ __nv_bfloat16 sm_raw[];

    const int tid  = threadIdx.x;
    const int lane = tid & 31;
    const int wid  = tid >> 5;
    const int wm   = wid >> 2;   // 0..1
    const int wn   = wid & 3;    // 0..3

    // grouped block swizzle for L2 reuse
    const int grid_m = M / BM, grid_n = N / BN;
    const int GRP = 8;
    int pid = blockIdx.x;
    int per = GRP * grid_n;
    int grp = pid / per;
    int fm = grp * GRP;
    int gs = grid_m - fm; if (gs > GRP) gs = GRP;
    int pin = pid % per;
    const int bm = (fm + (pin % gs)) * BM;
    const int bn = (pin / gs) * BN;

    const __nv_bfloat16* gsrc[4];
    gsrc[0] = Ah + (size_t)bm * K;
    gsrc[1] = Al + (size_t)bm * K;
    gsrc[2] = Bh + (size_t)bn * K;
    gsrc[3] = Bl + (size_t)bn * K;

    float acc[4][4][4];
#pragma unroll
    for (int a = 0; a < 4; a++)
#pragma unroll
        for (int b = 0; b < 4; b++)
#pragma unroll
            for (int c = 0; c < 4; c++) acc[a][b][c] = 0.0f;

    const int KT = K / BK;

    auto load_stage = [&](int buf, int kt) {
        if (kt < KT) {
            __nv_bfloat16* base = sm_raw + buf * 4 * TILE_ELEMS;
#pragma unroll
            for (int m = 0; m < 4; m++) {
#pragma unroll
                for (int j = 0; j < 2; j++) {
                    int chunk = tid + j * 256;          // 0..511
                    int row = chunk >> 2;
                    int col = (chunk & 3) * 8;
                    uint32_t dst = smem_u32(base + m * TILE_ELEMS + row * LDA + col);
                    const __nv_bfloat16* src = gsrc[m] + (size_t)row * K + (size_t)kt * BK + col;
                    CP_ASYNC16(dst, src);
                }
            }
        }
        CP_COMMIT();
    };

    load_stage(0, 0);
    load_stage(1, 1);

    const int lrow = lane & 15;
    const int lkof = (lane >> 4) << 3;

    int buf = 0;
    for (int kt = 0; kt < KT; ++kt) {
        CP_WAIT1();              // group kt complete (issued 2 iters ahead)
        __syncthreads();         // single barrier: visibility + WAR protection
        // prefetch kt+2 into the buffer last read at kt-1
        int nbuf = buf + 2; if (nbuf >= NSTAGE) nbuf -= NSTAGE;
        load_stage(nbuf, kt + 2);

        const __nv_bfloat16* sAh = sm_raw + buf * 4 * TILE_ELEMS;
        const __nv_bfloat16* sAl = sAh + TILE_ELEMS;
        const __nv_bfloat16* sBh = sAl + TILE_ELEMS;
        const __nv_bfloat16* sBl = sBh + TILE_ELEMS;

#pragma unroll
        for (int kk = 0; kk < 2; ++kk) {
            uint32_t ah[4][4], al[4][4], bh[4][2], bl[4][2];
            int kcol = kk * 16 + lkof;
#pragma unroll
            for (int mt = 0; mt < 4; mt++) {
                int r = wm * 64 + mt * 16 + lrow;
                ldsm_x4(ah[mt], smem_u32(sAh + r * LDA + kcol));
                ldsm_x4(al[mt], smem_u32(sAl + r * LDA + kcol));
            }
#pragma unroll
            for (int p = 0; p < 2; p++) {
                uint32_t t0[4], t1[4];
                int r = wn * 32 + p * 16 + lrow;
                ldsm_x4(t0, smem_u32(sBh + r * LDA + kcol));
                ldsm_x4(t1, smem_u32(sBl + r * LDA + kcol));
                bh[2 * p][0] = t0[0]; bh[2 * p + 1][0] = t0[1];
                bh[2 * p][1] = t0[2]; bh[2 * p + 1][1] = t0[3];
                bl[2 * p][0] = t1[0]; bl[2 * p + 1][0] = t1[1];
                bl[2 * p][1] = t1[2]; bl[2 * p + 1][1] = t1[3];
            }
#pragma unroll
            for (int mt = 0; mt < 4; mt++) {
#pragma unroll
                for (int nt = 0; nt < 4; nt++) {
                    mma_bf16(acc[mt][nt], ah[mt], bh[nt]);
                    mma_bf16(acc[mt][nt], ah[mt], bl[nt]);
                    mma_bf16(acc[mt][nt], al[mt], bh[nt]);
                }
            }
        }
        buf = buf + 1 == NSTAGE ? 0 : buf + 1;
    }

    // epilogue
#pragma unroll
    for (int mt = 0; mt < 4; mt++) {
        int r = bm + wm * 64 + mt * 16 + (lane >> 2);
#pragma unroll
        for (int nt = 0; nt < 4; nt++) {
            int c = bn + wn * 32 + nt * 8 + ((lane & 3) << 1);
            float* p0 = C + (size_t)r * N + c;
            float* p1 = p0 + (size_t)8 * N;
            if (accumulate) {
                p0[0] += acc[mt][nt][0]; p0[1] += acc[mt][nt][1];
                p1[0] += acc[mt][nt][2]; p1[1] += acc[mt][nt][3];
            } else {
                p0[0] = acc[mt][nt][0]; p0[1] = acc[mt][nt][1];
                p1[0] = acc[mt][nt][2]; p1[1] = acc[mt][nt][3];
            }
        }
    }
}

// ------------------------------ host ----------------------------------------
static void* sym_addr(const void* s) {
    void* p = nullptr;
    cudaGetSymbolAddress(&p, s);
    return p;
}

extern "C" void kernel_launch(void* const* d_in, const int* in_sizes, int n_in,
                              void* d_out, int out_size) {
    (void)in_sizes; (void)n_in; (void)out_size;
    const float* x   = (const float*)d_in[0];
    // d_in[1] = router_weight: mathematically a no-op (comb_w == 1), unused.
    const float* shg = (const float*)d_in[2];
    const float* shu = (const float*)d_in[3];
    const float* shd = (const float*)d_in[4];
    const float* rg  = (const float*)d_in[5];
    const float* ru  = (const float*)d_in[6];
    const float* rd  = (const float*)d_in[7];
    float* out = (float*)d_out;

    cudaFuncSetAttribute(gemm3x_kernel, cudaFuncAttributeMaxDynamicSharedMemorySize, SMEM_BYTES);

    __nv_bfloat16* XH = (__nv_bfloat16*)sym_addr(g_XH);
    __nv_bfloat16* XL = (__nv_bfloat16*)sym_addr(g_XL);
    __nv_bfloat16* SHGU_H = (__nv_bfloat16*)sym_addr(g_SHGU_H);
    __nv_bfloat16* SHGU_L = (__nv_bfloat16*)sym_addr(g_SHGU_L);
    __nv_bfloat16* SHD_H = (__nv_bfloat16*)sym_addr(g_SHD_H);
    __nv_bfloat16* SHD_L = (__nv_bfloat16*)sym_addr(g_SHD_L);
    __nv_bfloat16* RGU_H = (__nv_bfloat16*)sym_addr(g_RGU_H);
    __nv_bfloat16* RGU_L = (__nv_bfloat16*)sym_addr(g_RGU_L);
    __nv_bfloat16* RD_H = (__nv_bfloat16*)sym_addr(g_RD_H);
    __nv_bfloat16* RD_L = (__nv_bfloat16*)sym_addr(g_RD_L);
    float* GU  = (float*)sym_addr(g_GU);
    float* GUR = (float*)sym_addr(g_GUR);
    __nv_bfloat16* HSH_H = (__nv_bfloat16*)sym_addr(g_HSH_H);
    __nv_bfloat16* HSH_L = (__nv_bfloat16*)sym_addr(g_HSH_L);
    __nv_bfloat16* HR_H = (__nv_bfloat16*)sym_addr(g_HR_H);
    __nv_bfloat16* HR_L = (__nv_bfloat16*)sym_addr(g_HR_L);

    const int T = TOKENS;

    auto gemm = [&](const __nv_bfloat16* Ah, const __nv_bfloat16* Al,
                    const __nv_bfloat16* Bh, const __nv_bfloat16* Bl,
                    float* Cc, int M, int N, int K, int acc) {
        dim3 grid((M / BM) * (N / BN));
        gemm3x_kernel<<<grid, 256, SMEM_BYTES>>>(Ah, Al, Bh, Bl, Cc, M, N, K, acc);
    };

    // idx0: all weight splits in one launch
    {
        size_t total = 3 * W1 + 3 * R1;
        split_weights_kernel<<<(unsigned)((total + 255) / 256), 256>>>(
            shg, shu, shd, rg, ru, rd,
            SHGU_H, SHGU_L, SHD_H, SHD_L, RGU_H, RGU_L, RD_H, RD_L);
    }
    // idx1: x split
    {
        int n4 = T * HIDDEN / 4;
        split_x_kernel<<<(n4 + 255) / 256, 256>>>(x, XH, XL, n4);
    }

    // ---- routed chain first (writes out, acc=0) ----
    // idx2: routed fused gate+up GEMM  [T, 2*MOE_INTER]
    gemm(XH, XL, RGU_H, RGU_L, GUR, T, 2 * MOE_INTER, HIDDEN, 0);
    // idx3: routed swiglu
    {
        int n4 = T * MOE_INTER / 4;
        swiglu_split_kernel<<<(n4 + 255) / 256, 256>>>(GUR, HR_H, HR_L, MOE_INTER / 4, n4);
    }
    // idx4: routed down-projection -> out (acc=0)
    gemm(HR_H, HR_L, RD_H, RD_L, out, T, HIDDEN, MOE_INTER, 0);

    // ---- shared chain (accumulates into out) ----
    // idx5: BIG fused gate+up GEMM [T, 2*INTER]  <- ncu -s 5 -c 1 captures this
    gemm(XH, XL, SHGU_H, SHGU_L, GU, T, 2 * INTER, HIDDEN, 0);
    // idx6: shared swiglu
    {
        int n4 = T * INTER / 4;
        swiglu_split_kernel<<<(n4 + 255) / 256, 256>>>(GU, HSH_H, HSH_L, INTER / 4, n4);
    }
    // idx7: shared down-projection, accumulate into out
    gemm(HSH_H, HSH_L, SHD_H, SHD_L, out, T, HIDDEN, INTER, 1);
}

// round 13
// speedup vs baseline: 1.0001x; 1.0001x over previous
#include <cuda_runtime.h>
#include <cuda_bf16.h>
#include <cstdint>
#include <cstddef>

// ---------------------------------------------------------------------------
// DeepseekV3MoE on GB300 (sm_103 ptxas target: tcgen05 unavailable -> mma.sync).
// Router is a mathematical no-op (comb_w == 1 exactly):
//   out = swiglu_mlp(x; sh_*) + swiglu_mlp(x; r_*)
// 3xBF16 split GEMMs (hi*hi + hi*lo + lo*hi), fp32 accumulate, rel_err ~4e-5.
// This round: 3-stage cp.async pipeline w/ single barrier per K-step,
// gate+up fused into one GEMM (N doubled), launch order arranged so ncu
// (-s 5 -c 1) profiles the big shared up-projection GEMM.
// ---------------------------------------------------------------------------

#define HIDDEN    2048
#define INTER     8192
#define MOE_INTER 1024
#define TOKENS    (4 * 2048)

#define BM 128
#define BN 128
#define BK 32
#define LDA 40                 // BK + 8 pad: conflict-free ldmatrix
#define TILE_ELEMS (BM * LDA)
#define NSTAGE 3
#define SMEM_BYTES (NSTAGE * 4 * TILE_ELEMS * 2)   // 122880

// ------------------------------ scratch (device globals) -------------------
__device__ __align__(256) __nv_bfloat16 g_XH[TOKENS * HIDDEN];
__device__ __align__(256) __nv_bfloat16 g_XL[TOKENS * HIDDEN];

// gate+up fused weight splits: rows [0,INTER) = gate, [INTER,2*INTER) = up
__device__ __align__(256) __nv_bfloat16 g_SHGU_H[2 * INTER * HIDDEN];
__device__ __align__(256) __nv_bfloat16 g_SHGU_L[2 * INTER * HIDDEN];
__device__ __align__(256) __nv_bfloat16 g_SHD_H[HIDDEN * INTER];
__device__ __align__(256) __nv_bfloat16 g_SHD_L[HIDDEN * INTER];

__device__ __align__(256) __nv_bfloat16 g_RGU_H[2 * MOE_INTER * HIDDEN];
__device__ __align__(256) __nv_bfloat16 g_RGU_L[2 * MOE_INTER * HIDDEN];
__device__ __align__(256) __nv_bfloat16 g_RD_H[HIDDEN * MOE_INTER];
__device__ __align__(256) __nv_bfloat16 g_RD_L[HIDDEN * MOE_INTER];

__device__ __align__(256) float g_GU[(size_t)TOKENS * 2 * INTER];    // 512MB
__device__ __align__(256) __nv_bfloat16 g_HSH_H[(size_t)TOKENS * INTER];
__device__ __align__(256) __nv_bfloat16 g_HSH_L[(size_t)TOKENS * INTER];

__device__ __align__(256) float g_GUR[(size_t)TOKENS * 2 * MOE_INTER];
__device__ __align__(256) __nv_bfloat16 g_HR_H[(size_t)TOKENS * MOE_INTER];
__device__ __align__(256) __nv_bfloat16 g_HR_L[(size_t)TOKENS * MOE_INTER];

// ------------------------------ device helpers -----------------------------
__device__ __forceinline__ uint32_t smem_u32(const void* p) {
    return (uint32_t)__cvta_generic_to_shared(p);
}
__device__ __forceinline__ void ldsm_x4(uint32_t r[4], uint32_t addr) {
    asm volatile("ldmatrix.sync.aligned.m8n8.x4.shared.b16 {%0,%1,%2,%3}, [%4];"
                 : "=r"(r[0]), "=r"(r[1]), "=r"(r[2]), "=r"(r[3]) : "r"(addr));
}
__device__ __forceinline__ void mma_bf16(float c[4], const uint32_t a[4], const uint32_t b[2]) {
    asm volatile(
        "mma.sync.aligned.m16n8k16.row.col.f32.bf16.bf16.f32 "
        "{%0,%1,%2,%3}, {%4,%5,%6,%7}, {%8,%9}, {%0,%1,%2,%3};"
        : "+f"(c[0]), "+f"(c[1]), "+f"(c[2]), "+f"(c[3])
        : "r"(a[0]), "r"(a[1]), "r"(a[2]), "r"(a[3]), "r"(b[0]), "r"(b[1]));
}
#define CP_ASYNC16(dst, src) \
    asm volatile("cp.async.cg.shared.global [%0], [%1], 16;" :: "r"(dst), "l"(src))
#define CP_COMMIT() asm volatile("cp.async.commit_group;")
#define CP_WAIT1()  asm volatile("cp.async.wait_group 1;")

// ------------------------------ split helpers ------------------------------
__device__ __forceinline__ void split4(float4 v, __nv_bfloat162* hp, __nv_bfloat162* lp,
                                       size_t i2) {
    __nv_bfloat16 h0 = __float2bfloat16(v.x);
    __nv_bfloat16 h1 = __float2bfloat16(v.y);
    __nv_bfloat16 h2 = __float2bfloat16(v.z);
    __nv_bfloat16 h3 = __float2bfloat16(v.w);
    __nv_bfloat16 l0 = __float2bfloat16(v.x - __bfloat162float(h0));
    __nv_bfloat16 l1 = __float2bfloat16(v.y - __bfloat162float(h1));
    __nv_bfloat16 l2 = __float2bfloat16(v.z - __bfloat162float(h2));
    __nv_bfloat16 l3 = __float2bfloat16(v.w - __bfloat162float(h3));
    hp[i2]     = __nv_bfloat162(h0, h1);
    hp[i2 + 1] = __nv_bfloat162(h2, h3);
    lp[i2]     = __nv_bfloat162(l0, l1);
    lp[i2 + 1] = __nv_bfloat162(l2, l3);
}

// one kernel splits all six weight tensors (keeps launch count down and
// puts the big GEMM at ncu's capture index)
#define W1 ((size_t)INTER * HIDDEN / 4)        // f4 per big weight
#define R1 ((size_t)MOE_INTER * HIDDEN / 4)    // f4 per routed weight
__global__ void split_weights_kernel(
    const float* __restrict__ shg, const float* __restrict__ shu,
    const float* __restrict__ shd, const float* __restrict__ rg,
    const float* __restrict__ ru,  const float* __restrict__ rd,
    __nv_bfloat16* __restrict__ SHGU_H, __nv_bfloat16* __restrict__ SHGU_L,
    __nv_bfloat16* __restrict__ SHD_H,  __nv_bfloat16* __restrict__ SHD_L,
    __nv_bfloat16* __restrict__ RGU_H,  __nv_bfloat16* __restrict__ RGU_L,
    __nv_bfloat16* __restrict__ RD_H,   __nv_bfloat16* __restrict__ RD_L) {
    size_t i = (size_t)blockIdx.x * blockDim.x + threadIdx.x;
    const size_t total = 3 * W1 + 3 * R1;
    if (i >= total) return;
    const float* src; __nv_bfloat16* hi; __nv_bfloat16* lo; size_t off;
    if (i < W1)               { src = shg; hi = SHGU_H; lo = SHGU_L; off = i; }
    else if (i < 2 * W1)      { src = shu; hi = SHGU_H; lo = SHGU_L; off = i; src -= W1 * 4 / 1, src = shu; off = i; }
    else if (i < 3 * W1)      { src = shd; hi = SHD_H;  lo = SHD_L;  off = i - 2 * W1; }
    else if (i < 3 * W1 + R1) { src = rg;  hi = RGU_H;  lo = RGU_L;  off = i - 3 * W1; }
    else if (i < 3 * W1 + 2 * R1) { src = ru; hi = RGU_H; lo = RGU_L; off = i - 3 * W1; }
    else                      { src = rd;  hi = RD_H;   lo = RD_L;   off = i - 3 * W1 - 2 * R1; }
    // fix source index for the concatenated cases
    size_t sidx;
    if (i < W1)                    sidx = i;
    else if (i < 2 * W1)           sidx = i - W1;            // shu -> second half of SHGU
    else if (i < 3 * W1)           sidx = off;
    else if (i < 3 * W1 + R1)      sidx = off;
    else if (i < 3 * W1 + 2 * R1)  sidx = i - (3 * W1 + R1); // ru -> second half of RGU
    else                           sidx = off;
    float4 v = reinterpret_cast<const float4*>(src)[sidx];
    split4(v, reinterpret_cast<__nv_bfloat162*>(hi),
              reinterpret_cast<__nv_bfloat162*>(lo), 2 * off);
}

__global__ void split_x_kernel(const float* __restrict__ src,
                               __nv_bfloat16* __restrict__ hi,
                               __nv_bfloat16* __restrict__ lo, int n4) {
    int i = blockIdx.x * blockDim.x + threadIdx.x;
    if (i >= n4) return;
    float4 v = reinterpret_cast<const float4*>(src)[i];
    split4(v, reinterpret_cast<__nv_bfloat162*>(hi),
              reinterpret_cast<__nv_bfloat162*>(lo), 2 * (size_t)i);
}

// swiglu over fused C[T, 2*I] (gate cols [0,I), up cols [I,2I)) -> hi/lo [T, I]
__global__ void swiglu_split_kernel(const float* __restrict__ C,
                                    __nv_bfloat16* __restrict__ hi,
                                    __nv_bfloat16* __restrict__ lo,
                                    int I4, int n4) {
    int i = blockIdx.x * blockDim.x + threadIdx.x;
    if (i >= n4) return;
    int t = i / I4, r = i % I4;
    const float4* gp = reinterpret_cast<const float4*>(C + (size_t)t * 2 * (I4 * 4)) + r;
    float4 gv = gp[0];
    float4 uv = gp[I4];
    float h[4];
    h[0] = gv.x * (1.0f / (1.0f + expf(-gv.x))) * uv.x;
    h[1] = gv.y * (1.0f / (1.0f + expf(-gv.y))) * uv.y;
    h[2] = gv.z * (1.0f / (1.0f + expf(-gv.z))) * uv.z;
    h[3] = gv.w * (1.0f / (1.0f + expf(-gv.w))) * uv.w;
    float4 hv = make_float4(h[0], h[1], h[2], h[3]);
    split4(hv, reinterpret_cast<__nv_bfloat162*>(hi),
               reinterpret_cast<__nv_bfloat162*>(lo), 2 * (size_t)i);
}

// ------------------------------ 3xBF16 GEMM ---------------------------------
// C[M,N] = A[M,K] @ B[N,K]^T; 3-stage cp.async pipeline, one barrier/K-step.
__global__ void __launch_bounds__(256, 1)
gemm3x_kernel(const __nv_bfloat16* __restrict__ Ah, const __nv_bfloat16* __restrict__ Al,
              const __nv_bfloat16* __restrict__ Bh, const __nv_bfloat16* __restrict__ Bl,
              float* __restrict__ C, int M, int N, int K, int accumulate) {
    extern __shared__ __nv_bfloat16 sm_raw[];

    const int tid  = threadIdx.x;
    const int lane = tid & 31;
    const int wid  = tid >> 5;
    const int wm   = wid >> 2;   // 0..1
    const int wn   = wid & 3;    // 0..3

    // grouped block swizzle for L2 reuse
    const int grid_m = M / BM, grid_n = N / BN;
    const int GRP = 8;
    int pid = blockIdx.x;
    int per = GRP * grid_n;
    int grp = pid / per;
    int fm = grp * GRP;
    int gs = grid_m - fm; if (gs > GRP) gs = GRP;
    int pin = pid % per;
    const int bm = (fm + (pin % gs)) * BM;
    const int bn = (pin / gs) * BN;

    const __nv_bfloat16* gsrc[4];
    gsrc[0] = Ah + (size_t)bm * K;
    gsrc[1] = Al + (size_t)bm * K;
    gsrc[2] = Bh + (size_t)bn * K;
    gsrc[3] = Bl + (size_t)bn * K;

    float acc[4][4][4];
#pragma unroll
    for (int a = 0; a < 4; a++)
#pragma unroll
        for (int b = 0; b < 4; b++)
#pragma unroll
            for (int c = 0; c < 4; c++) acc[a][b][c] = 0.0f;

    const int KT = K / BK;

    auto load_stage = [&](int buf, int kt) {
        if (kt < KT) {
            __nv_bfloat16* base = sm_raw + buf * 4 * TILE_ELEMS;
#pragma unroll
            for (int m = 0; m < 4; m++) {
#pragma unroll
                for (int j = 0; j < 2; j++) {
                    int chunk = tid + j * 256;          // 0..511
                    int row = chunk >> 2;
                    int col = (chunk & 3) * 8;
                    uint32_t dst = smem_u32(base + m * TILE_ELEMS + row * LDA + col);
                    const __nv_bfloat16* src = gsrc[m] + (size_t)row * K + (size_t)kt * BK + col;
                    CP_ASYNC16(dst, src);
                }
            }
        }
        CP_COMMIT();
    };

    load_stage(0, 0);
    load_stage(1, 1);

    const int lrow = lane & 15;
    const int lkof = (lane >> 4) << 3;

    int buf = 0;
    for (int kt = 0; kt < KT; ++kt) {
        CP_WAIT1();              // group kt complete (issued 2 iters ahead)
        __syncthreads();         // single barrier: visibility + WAR protection
        // prefetch kt+2 into the buffer last read at kt-1
        int nbuf = buf + 2; if (nbuf >= NSTAGE) nbuf -= NSTAGE;
        load_stage(nbuf, kt + 2);

        const __nv_bfloat16* sAh = sm_raw + buf * 4 * TILE_ELEMS;
        const __nv_bfloat16* sAl = sAh + TILE_ELEMS;
        const __nv_bfloat16* sBh = sAl + TILE_ELEMS;
        const __nv_bfloat16* sBl = sBh + TILE_ELEMS;

#pragma unroll
        for (int kk = 0; kk < 2; ++kk) {
            uint32_t ah[4][4], al[4][4], bh[4][2], bl[4][2];
            int kcol = kk * 16 + lkof;
#pragma unroll
            for (int mt = 0; mt < 4; mt++) {
                int r = wm * 64 + mt * 16 + lrow;
                ldsm_x4(ah[mt], smem_u32(sAh + r * LDA + kcol));
                ldsm_x4(al[mt], smem_u32(sAl + r * LDA + kcol));
            }
#pragma unroll
            for (int p = 0; p < 2; p++) {
                uint32_t t0[4], t1[4];
                int r = wn * 32 + p * 16 + lrow;
                ldsm_x4(t0, smem_u32(sBh + r * LDA + kcol));
                ldsm_x4(t1, smem_u32(sBl + r * LDA + kcol));
                bh[2 * p][0] = t0[0]; bh[2 * p + 1][0] = t0[1];
                bh[2 * p][1] = t0[2]; bh[2 * p + 1][1] = t0[3];
                bl[2 * p][0] = t1[0]; bl[2 * p + 1][0] = t1[1];
                bl[2 * p][1] = t1[2]; bl[2 * p + 1][1] = t1[3];
            }
#pragma unroll
            for (int mt = 0; mt < 4; mt++) {
#pragma unroll
                for (int nt = 0; nt < 4; nt++) {
                    mma_bf16(acc[mt][nt], ah[mt], bh[nt]);
                    mma_bf16(acc[mt][nt], ah[mt], bl[nt]);
                    mma_bf16(acc[mt][nt], al[mt], bh[nt]);
                }
            }
        }
        buf = buf + 1 == NSTAGE ? 0 : buf + 1;
    }

    // epilogue
#pragma unroll
    for (int mt = 0; mt < 4; mt++) {
        int r = bm + wm * 64 + mt * 16 + (lane >> 2);
#pragma unroll
        for (int nt = 0; nt < 4; nt++) {
            int c = bn + wn * 32 + nt * 8 + ((lane & 3) << 1);
            float* p0 = C + (size_t)r * N + c;
            float* p1 = p0 + (size_t)8 * N;
            if (accumulate) {
                p0[0] += acc[mt][nt][0]; p0[1] += acc[mt][nt][1];
                p1[0] += acc[mt][nt][2]; p1[1] += acc[mt][nt][3];
            } else {
                p0[0] = acc[mt][nt][0]; p0[1] = acc[mt][nt][1];
                p1[0] = acc[mt][nt][2]; p1[1] = acc[mt][nt][3];
            }
        }
    }
}

// ------------------------------ host ----------------------------------------
static void* sym_addr(const void* s) {
    void* p = nullptr;
    cudaGetSymbolAddress(&p, s);
    return p;
}

extern "C" void kernel_launch(void* const* d_in, const int* in_sizes, int n_in,
                              void* d_out, int out_size) {
    (void)in_sizes; (void)n_in; (void)out_size;
    const float* x   = (const float*)d_in[0];
    // d_in[1] = router_weight: mathematically a no-op (comb_w == 1), unused.
    const float* shg = (const float*)d_in[2];
    const float* shu = (const float*)d_in[3];
    const float* shd = (const float*)d_in[4];
    const float* rg  = (const float*)d_in[5];
    const float* ru  = (const float*)d_in[6];
    const float* rd  = (const float*)d_in[7];
    float* out = (float*)d_out;

    cudaFuncSetAttribute(gemm3x_kernel, cudaFuncAttributeMaxDynamicSharedMemorySize, SMEM_BYTES);

    __nv_bfloat16* XH = (__nv_bfloat16*)sym_addr(g_XH);
    __nv_bfloat16* XL = (__nv_bfloat16*)sym_addr(g_XL);
    __nv_bfloat16* SHGU_H = (__nv_bfloat16*)sym_addr(g_SHGU_H);
    __nv_bfloat16* SHGU_L = (__nv_bfloat16*)sym_addr(g_SHGU_L);
    __nv_bfloat16* SHD_H = (__nv_bfloat16*)sym_addr(g_SHD_H);
    __nv_bfloat16* SHD_L = (__nv_bfloat16*)sym_addr(g_SHD_L);
    __nv_bfloat16* RGU_H = (__nv_bfloat16*)sym_addr(g_RGU_H);
    __nv_bfloat16* RGU_L = (__nv_bfloat16*)sym_addr(g_RGU_L);
    __nv_bfloat16* RD_H = (__nv_bfloat16*)sym_addr(g_RD_H);
    __nv_bfloat16* RD_L = (__nv_bfloat16*)sym_addr(g_RD_L);
    float* GU  = (float*)sym_addr(g_GU);
    float* GUR = (float*)sym_addr(g_GUR);
    __nv_bfloat16* HSH_H = (__nv_bfloat16*)sym_addr(g_HSH_H);
    __nv_bfloat16* HSH_L = (__nv_bfloat16*)sym_addr(g_HSH_L);
    __nv_bfloat16* HR_H = (__nv_bfloat16*)sym_addr(g_HR_H);
    __nv_bfloat16* HR_L = (__nv_bfloat16*)sym_addr(g_HR_L);

    const int T = TOKENS;

    auto gemm = [&](const __nv_bfloat16* Ah, const __nv_bfloat16* Al,
                    const __nv_bfloat16* Bh, const __nv_bfloat16* Bl,
                    float* Cc, int M, int N, int K, int acc) {
        dim3 grid((M / BM) * (N / BN));
        gemm3x_kernel<<<grid, 256, SMEM_BYTES>>>(Ah, Al, Bh, Bl, Cc, M, N, K, acc);
    };

    // idx0: all weight splits in one launch
    {
        size_t total = 3 * W1 + 3 * R1;
        split_weights_kernel<<<(unsigned)((total + 255) / 256), 256>>>(
            shg, shu, shd, rg, ru, rd,
            SHGU_H, SHGU_L, SHD_H, SHD_L, RGU_H, RGU_L, RD_H, RD_L);
    }
    // idx1: x split
    {
        int n4 = T * HIDDEN / 4;
        split_x_kernel<<<(n4 + 255) / 256, 256>>>(x, XH, XL, n4);
    }

    // ---- routed chain first (writes out, acc=0) ----
    // idx2: routed fused gate+up GEMM  [T, 2*MOE_INTER]
    gemm(XH, XL, RGU_H, RGU_L, GUR, T, 2 * MOE_INTER, HIDDEN, 0);
    // idx3: routed swiglu
    {
        int n4 = T * MOE_INTER / 4;
        swiglu_split_kernel<<<(n4 + 255) / 256, 256>>>(GUR, HR_H, HR_L, MOE_INTER / 4, n4);
    }
    // idx4: routed down-projection -> out (acc=0)
    gemm(HR_H, HR_L, RD_H, RD_L, out, T, HIDDEN, MOE_INTER, 0);

    // ---- shared chain (accumulates into out) ----
    // idx5: BIG fused gate+up GEMM [T, 2*INTER]  <- ncu -s 5 -c 1 captures this
    gemm(XH, XL, SHGU_H, SHGU_L, GU, T, 2 * INTER, HIDDEN, 0);
    // idx6: shared swiglu
    {
        int n4 = T * INTER / 4;
        swiglu_split_kernel<<<(n4 + 255) / 256, 256>>>(GU, HSH_H, HSH_L, INTER / 4, n4);
    }
    // idx7: shared down-projection, accumulate into out
    gemm(HSH_H, HSH_L, SHD_H, SHD_L, out, T, HIDDEN, INTER, 1);
}

// round 14
// speedup vs baseline: 1.0005x; 1.0004x over previous
#include <cuda_runtime.h>
#include <cuda_bf16.h>
#include <cstdint>
#include <cstddef>

// ---------------------------------------------------------------------------
// DeepseekV3MoE on GB300 (sm_103 ptxas target: tcgen05 unavailable -> mma.sync).
// Router is a mathematical no-op (comb_w == 1 exactly):
//   out = swiglu_mlp(x; sh_*) + swiglu_mlp(x; r_*)
// 3xBF16 split GEMMs (hi*hi + hi*lo + lo*hi), fp32 accumulate, rel_err ~4e-5.
// This round: 3-stage cp.async pipeline w/ single barrier per K-step,
// gate+up fused into one GEMM (N doubled), launch order arranged so ncu
// (-s 5 -c 1) profiles the big shared up-projection GEMM.
// ---------------------------------------------------------------------------

#define HIDDEN    2048
#define INTER     8192
#define MOE_INTER 1024
#define TOKENS    (4 * 2048)

#define BM 128
#define BN 128
#define BK 32
#define LDA 40                 // BK + 8 pad: conflict-free ldmatrix
#define TILE_ELEMS (BM * LDA)
#define NSTAGE 3
#define SMEM_BYTES (NSTAGE * 4 * TILE_ELEMS * 2)   // 122880

// ------------------------------ scratch (device globals) -------------------
__device__ __align__(256) __nv_bfloat16 g_XH[TOKENS * HIDDEN];
__device__ __align__(256) __nv_bfloat16 g_XL[TOKENS * HIDDEN];

// gate+up fused weight splits: rows [0,INTER) = gate, [INTER,2*INTER) = up
__device__ __align__(256) __nv_bfloat16 g_SHGU_H[2 * INTER * HIDDEN];
__device__ __align__(256) __nv_bfloat16 g_SHGU_L[2 * INTER * HIDDEN];
__device__ __align__(256) __nv_bfloat16 g_SHD_H[HIDDEN * INTER];
__device__ __align__(256) __nv_bfloat16 g_SHD_L[HIDDEN * INTER];

__device__ __align__(256) __nv_bfloat16 g_RGU_H[2 * MOE_INTER * HIDDEN];
__device__ __align__(256) __nv_bfloat16 g_RGU_L[2 * MOE_INTER * HIDDEN];
__device__ __align__(256) __nv_bfloat16 g_RD_H[HIDDEN * MOE_INTER];
__device__ __align__(256) __nv_bfloat16 g_RD_L[HIDDEN * MOE_INTER];

__device__ __align__(256) float g_GU[(size_t)TOKENS * 2 * INTER];    // 512MB
__device__ __align__(256) __nv_bfloat16 g_HSH_H[(size_t)TOKENS * INTER];
__device__ __align__(256) __nv_bfloat16 g_HSH_L[(size_t)TOKENS * INTER];

__device__ __align__(256) float g_GUR[(size_t)TOKENS * 2 * MOE_INTER];
__device__ __align__(256) __nv_bfloat16 g_HR_H[(size_t)TOKENS * MOE_INTER];
__device__ __align__(256) __nv_bfloat16 g_HR_L[(size_t)TOKENS * MOE_INTER];

// ------------------------------ device helpers -----------------------------
__device__ __forceinline__ uint32_t smem_u32(const void* p) {
    return (uint32_t)__cvta_generic_to_shared(p);
}
__device__ __forceinline__ void ldsm_x4(uint32_t r[4], uint32_t addr) {
    asm volatile("ldmatrix.sync.aligned.m8n8.x4.shared.b16 {%0,%1,%2,%3}, [%4];"
                 : "=r"(r[0]), "=r"(r[1]), "=r"(r[2]), "=r"(r[3]) : "r"(addr));
}
__device__ __forceinline__ void mma_bf16(float c[4], const uint32_t a[4], const uint32_t b[2]) {
    asm volatile(
        "mma.sync.aligned.m16n8k16.row.col.f32.bf16.bf16.f32 "
        "{%0,%1,%2,%3}, {%4,%5,%6,%7}, {%8,%9}, {%0,%1,%2,%3};"
        : "+f"(c[0]), "+f"(c[1]), "+f"(c[2]), "+f"(c[3])
        : "r"(a[0]), "r"(a[1]), "r"(a[2]), "r"(a[3]), "r"(b[0]), "r"(b[1]));
}
#define CP_ASYNC16(dst, src) \
    asm volatile("cp.async.cg.shared.global [%0], [%1], 16;" :: "r"(dst), "l"(src))
#define CP_COMMIT() asm volatile("cp.async.commit_group;")
#define CP_WAIT1()  asm volatile("cp.async.wait_group 1;")

// ------------------------------ split helpers ------------------------------
__device__ __forceinline__ void split4(float4 v, __nv_bfloat162* hp, __nv_bfloat162* lp,
                                       size_t i2) {
    __nv_bfloat16 h0 = __float2bfloat16(v.x);
    __nv_bfloat16 h1 = __float2bfloat16(v.y);
    __nv_bfloat16 h2 = __float2bfloat16(v.z);
    __nv_bfloat16 h3 = __float2bfloat16(v.w);
    __nv_bfloat16 l0 = __float2bfloat16(v.x - __bfloat162float(h0));
    __nv_bfloat16 l1 = __float2bfloat16(v.y - __bfloat162float(h1));
    __nv_bfloat16 l2 = __float2bfloat16(v.z - __bfloat162float(h2));
    __nv_bfloat16 l3 = __float2bfloat16(v.w - __bfloat162float(h3));
    hp[i2]     = __nv_bfloat162(h0, h1);
    hp[i2 + 1] = __nv_bfloat162(h2, h3);
    lp[i2]     = __nv_bfloat162(l0, l1);
    lp[i2 + 1] = __nv_bfloat162(l2, l3);
}

// one kernel splits all six weight tensors (keeps launch count down and
// puts the big GEMM at ncu's capture index)
#define W1 ((size_t)INTER * HIDDEN / 4)        // f4 per big weight
#define R1 ((size_t)MOE_INTER * HIDDEN / 4)    // f4 per routed weight
__global__ void split_weights_kernel(
    const float* __restrict__ shg, const float* __restrict__ shu,
    const float* __restrict__ shd, const float* __restrict__ rg,
    const float* __restrict__ ru,  const float* __restrict__ rd,
    __nv_bfloat16* __restrict__ SHGU_H, __nv_bfloat16* __restrict__ SHGU_L,
    __nv_bfloat16* __restrict__ SHD_H,  __nv_bfloat16* __restrict__ SHD_L,
    __nv_bfloat16* __restrict__ RGU_H,  __nv_bfloat16* __restrict__ RGU_L,
    __nv_bfloat16* __restrict__ RD_H,   __nv_bfloat16* __restrict__ RD_L) {
    size_t i = (size_t)blockIdx.x * blockDim.x + threadIdx.x;
    const size_t total = 3 * W1 + 3 * R1;
    if (i >= total) return;
    const float* src; __nv_bfloat16* hi; __nv_bfloat16* lo; size_t off;
    if (i < W1)               { src = shg; hi = SHGU_H; lo = SHGU_L; off = i; }
    else if (i < 2 * W1)      { src = shu; hi = SHGU_H; lo = SHGU_L; off = i; src -= W1 * 4 / 1, src = shu; off = i; }
    else if (i < 3 * W1)      { src = shd; hi = SHD_H;  lo = SHD_L;  off = i - 2 * W1; }
    else if (i < 3 * W1 + R1) { src = rg;  hi = RGU_H;  lo = RGU_L;  off = i - 3 * W1; }
    else if (i < 3 * W1 + 2 * R1) { src = ru; hi = RGU_H; lo = RGU_L; off = i - 3 * W1; }
    else                      { src = rd;  hi = RD_H;   lo = RD_L;   off = i - 3 * W1 - 2 * R1; }
    // fix source index for the concatenated cases
    size_t sidx;
    if (i < W1)                    sidx = i;
    else if (i < 2 * W1)           sidx = i - W1;            // shu -> second half of SHGU
    else if (i < 3 * W1)           sidx = off;
    else if (i < 3 * W1 + R1)      sidx = off;
    else if (i < 3 * W1 + 2 * R1)  sidx = i - (3 * W1 + R1); // ru -> second half of RGU
    else                           sidx = off;
    float4 v = reinterpret_cast<const float4*>(src)[sidx];
    split4(v, reinterpret_cast<__nv_bfloat162*>(hi),
              reinterpret_cast<__nv_bfloat162*>(lo), 2 * off);
}

__global__ void split_x_kernel(const float* __restrict__ src,
                               __nv_bfloat16* __restrict__ hi,
                               __nv_bfloat16* __restrict__ lo, int n4) {
    int i = blockIdx.x * blockDim.x + threadIdx.x;
    if (i >= n4) return;
    float4 v = reinterpret_cast<const float4*>(src)[i];
    split4(v, reinterpret_cast<__nv_bfloat162*>(hi),
              reinterpret_cast<__nv_bfloat162*>(lo), 2 * (size_t)i);
}

// swiglu over fused C[T, 2*I] (gate cols [0,I), up cols [I,2I)) -> hi/lo [T, I]
__global__ void swiglu_split_kernel(const float* __restrict__ C,
                                    __nv_bfloat16* __restrict__ hi,
                                    __nv_bfloat16* __restrict__ lo,
                                    int I4, int n4) {
    int i = blockIdx.x * blockDim.x + threadIdx.x;
    if (i >= n4) return;
    int t = i / I4, r = i % I4;
    const float4* gp = reinterpret_cast<const float4*>(C + (size_t)t * 2 * (I4 * 4)) + r;
    float4 gv = gp[0];
    float4 uv = gp[I4];
    float h[4];
    h[0] = gv.x * (1.0f / (1.0f + expf(-gv.x))) * uv.x;
    h[1] = gv.y * (1.0f / (1.0f + expf(-gv.y))) * uv.y;
    h[2] = gv.z * (1.0f / (1.0f + expf(-gv.z))) * uv.z;
    h[3] = gv.w * (1.0f / (1.0f + expf(-gv.w))) * uv.w;
    float4 hv = make_float4(h[0], h[1], h[2], h[3]);
    split4(hv, reinterpret_cast<__nv_bfloat162*>(hi),
               reinterpret_cast<__nv_bfloat162*>(lo), 2 * (size_t)i);
}

// ------------------------------ 3xBF16 GEMM ---------------------------------
// C[M,N] = A[M,K] @ B[N,K]^T; 3-stage cp.async pipeline, one barrier/K-step.
__global__ void __launch_bounds__(256, 1)
gemm3x_kernel(const __nv_bfloat16* __restrict__ Ah, const __nv_bfloat16* __restrict__ Al,
              const __nv_bfloat16* __restrict__ Bh, const __nv_bfloat16* __restrict__ Bl,
              float* __restrict__ C, int M, int N, int K, int accumulate) {
    extern __shared__ __nv_bfloat16 sm_raw[];

    const int tid  = threadIdx.x;
    const int lane = tid & 31;
    const int wid  = tid >> 5;
    const int wm   = wid >> 2;   // 0..1
    const int wn   = wid & 3;    // 0..3

    // grouped block swizzle for L2 reuse
    const int grid_m = M / BM, grid_n = N / BN;
    const int GRP = 8;
    int pid = blockIdx.x;
    int per = GRP * grid_n;
    int grp = pid / per;
    int fm = grp * GRP;
    int gs = grid_m - fm; if (gs > GRP) gs = GRP;
    int pin = pid % per;
    const int bm = (fm + (pin % gs)) * BM;
    const int bn = (pin / gs) * BN;

    const __nv_bfloat16* gsrc[4];
    gsrc[0] = Ah + (size_t)bm * K;
    gsrc[1] = Al + (size_t)bm * K;
    gsrc[2] = Bh + (size_t)bn * K;
    gsrc[3] = Bl + (size_t)bn * K;

    float acc[4][4][4];
#pragma unroll
    for (int a = 0; a < 4; a++)
#pragma unroll
        for (int b = 0; b < 4; b++)
#pragma unroll
            for (int c = 0; c < 4; c++) acc[a][b][c] = 0.0f;

    const int KT = K / BK;

    auto load_stage = [&](int buf, int kt) {
        if (kt < KT) {
            __nv_bfloat16* base = sm_raw + buf * 4 * TILE_ELEMS;
#pragma unroll
            for (int m = 0; m < 4; m++) {
#pragma unroll
                for (int j = 0; j < 2; j++) {
                    int chunk = tid + j * 256;          // 0..511
                    int row = chunk >> 2;
                    int col = (chunk & 3) * 8;
                    uint32_t dst = smem_u32(base + m * TILE_ELEMS + row * LDA + col);
                    const __nv_bfloat16* src = gsrc[m] + (size_t)row * K + (size_t)kt * BK + col;
                    CP_ASYNC16(dst, src);
                }
            }
        }
        CP_COMMIT();
    };

    load_stage(0, 0);
    load_stage(1, 1);

    const int lrow = lane & 15;
    const int lkof = (lane >> 4) << 3;

    int buf = 0;
    for (int kt = 0; kt < KT; ++kt) {
        CP_WAIT1();              // group kt complete (issued 2 iters ahead)
        __syncthreads();         // single barrier: visibility + WAR protection
        // prefetch kt+2 into the buffer last read at kt-1
        int nbuf = buf + 2; if (nbuf >= NSTAGE) nbuf -= NSTAGE;
        load_stage(nbuf, kt + 2);

        const __nv_bfloat16* sAh = sm_raw + buf * 4 * TILE_ELEMS;
        const __nv_bfloat16* sAl = sAh + TILE_ELEMS;
        const __nv_bfloat16* sBh = sAl + TILE_ELEMS;
        const __nv_bfloat16* sBl = sBh + TILE_ELEMS;

#pragma unroll
        for (int kk = 0; kk < 2; ++kk) {
            uint32_t ah[4][4], al[4][4], bh[4][2], bl[4][2];
            int kcol = kk * 16 + lkof;
#pragma unroll
            for (int mt = 0; mt < 4; mt++) {
                int r = wm * 64 + mt * 16 + lrow;
                ldsm_x4(ah[mt], smem_u32(sAh + r * LDA + kcol));
                ldsm_x4(al[mt], smem_u32(sAl + r * LDA + kcol));
            }
#pragma unroll
            for (int p = 0; p < 2; p++) {
                uint32_t t0[4], t1[4];
                int r = wn * 32 + p * 16 + lrow;
                ldsm_x4(t0, smem_u32(sBh + r * LDA + kcol));
                ldsm_x4(t1, smem_u32(sBl + r * LDA + kcol));
                bh[2 * p][0] = t0[0]; bh[2 * p + 1][0] = t0[1];
                bh[2 * p][1] = t0[2]; bh[2 * p + 1][1] = t0[3];
                bl[2 * p][0] = t1[0]; bl[2 * p + 1][0] = t1[1];
                bl[2 * p][1] = t1[2]; bl[2 * p + 1][1] = t1[3];
            }
#pragma unroll
            for (int mt = 0; mt < 4; mt++) {
#pragma unroll
                for (int nt = 0; nt < 4; nt++) {
                    mma_bf16(acc[mt][nt], ah[mt], bh[nt]);
                    mma_bf16(acc[mt][nt], ah[mt], bl[nt]);
                    mma_bf16(acc[mt][nt], al[mt], bh[nt]);
                }
            }
        }
        buf = buf + 1 == NSTAGE ? 0 : buf + 1;
    }

    // epilogue
#pragma unroll
    for (int mt = 0; mt < 4; mt++) {
        int r = bm + wm * 64 + mt * 16 + (lane >> 2);
#pragma unroll
        for (int nt = 0; nt < 4; nt++) {
            int c = bn + wn * 32 + nt * 8 + ((lane & 3) << 1);
            float* p0 = C + (size_t)r * N + c;
            float* p1 = p0 + (size_t)8 * N;
            if (accumulate) {
                p0[0] += acc[mt][nt][0]; p0[1] += acc[mt][nt][1];
                p1[0] += acc[mt][nt][2]; p1[1] += acc[mt][nt][3];
            } else {
                p0[0] = acc[mt][nt][0]; p0[1] = acc[mt][nt][1];
                p1[0] = acc[mt][nt][2]; p1[1] = acc[mt][nt][3];
            }
        }
    }
}

// ------------------------------ host ----------------------------------------
static void* sym_addr(const void* s) {
    void* p = nullptr;
    cudaGetSymbolAddress(&p, s);
    return p;
}

extern "C" void kernel_launch(void* const* d_in, const int* in_sizes, int n_in,
                              void* d_out, int out_size) {
    (void)in_sizes; (void)n_in; (void)out_size;
    const float* x   = (const float*)d_in[0];
    // d_in[1] = router_weight: mathematically a no-op (comb_w == 1), unused.
    const float* shg = (const float*)d_in[2];
    const float* shu = (const float*)d_in[3];
    const float* shd = (const float*)d_in[4];
    const float* rg  = (const float*)d_in[5];
    const float* ru  = (const float*)d_in[6];
    const float* rd  = (const float*)d_in[7];
    float* out = (float*)d_out;

    cudaFuncSetAttribute(gemm3x_kernel, cudaFuncAttributeMaxDynamicSharedMemorySize, SMEM_BYTES);

    __nv_bfloat16* XH = (__nv_bfloat16*)sym_addr(g_XH);
    __nv_bfloat16* XL = (__nv_bfloat16*)sym_addr(g_XL);
    __nv_bfloat16* SHGU_H = (__nv_bfloat16*)sym_addr(g_SHGU_H);
    __nv_bfloat16* SHGU_L = (__nv_bfloat16*)sym_addr(g_SHGU_L);
    __nv_bfloat16* SHD_H = (__nv_bfloat16*)sym_addr(g_SHD_H);
    __nv_bfloat16* SHD_L = (__nv_bfloat16*)sym_addr(g_SHD_L);
    __nv_bfloat16* RGU_H = (__nv_bfloat16*)sym_addr(g_RGU_H);
    __nv_bfloat16* RGU_L = (__nv_bfloat16*)sym_addr(g_RGU_L);
    __nv_bfloat16* RD_H = (__nv_bfloat16*)sym_addr(g_RD_H);
    __nv_bfloat16* RD_L = (__nv_bfloat16*)sym_addr(g_RD_L);
    float* GU  = (float*)sym_addr(g_GU);
    float* GUR = (float*)sym_addr(g_GUR);
    __nv_bfloat16* HSH_H = (__nv_bfloat16*)sym_addr(g_HSH_H);
    __nv_bfloat16* HSH_L = (__nv_bfloat16*)sym_addr(g_HSH_L);
    __nv_bfloat16* HR_H = (__nv_bfloat16*)sym_addr(g_HR_H);
    __nv_bfloat16* HR_L = (__nv_bfloat16*)sym_addr(g_HR_L);

    const int T = TOKENS;

    auto gemm = [&](const __nv_bfloat16* Ah, const __nv_bfloat16* Al,
                    const __nv_bfloat16* Bh, const __nv_bfloat16* Bl,
                    float* Cc, int M, int N, int K, int acc) {
        dim3 grid((M / BM) * (N / BN));
        gemm3x_kernel<<<grid, 256, SMEM_BYTES>>>(Ah, Al, Bh, Bl, Cc, M, N, K, acc);
    };

    // idx0: all weight splits in one launch
    {
        size_t total = 3 * W1 + 3 * R1;
        split_weights_kernel<<<(unsigned)((total + 255) / 256), 256>>>(
            shg, shu, shd, rg, ru, rd,
            SHGU_H, SHGU_L, SHD_H, SHD_L, RGU_H, RGU_L, RD_H, RD_L);
    }
    // idx1: x split
    {
        int n4 = T * HIDDEN / 4;
        split_x_kernel<<<(n4 + 255) / 256, 256>>>(x, XH, XL, n4);
    }

    // ---- routed chain first (writes out, acc=0) ----
    // idx2: routed fused gate+up GEMM  [T, 2*MOE_INTER]
    gemm(XH, XL, RGU_H, RGU_L, GUR, T, 2 * MOE_INTER, HIDDEN, 0);
    // idx3: routed swiglu
    {
        int n4 = T * MOE_INTER / 4;
        swiglu_split_kernel<<<(n4 + 255) / 256, 256>>>(GUR, HR_H, HR_L, MOE_INTER / 4, n4);
    }
    // idx4: routed down-projection -> out (acc=0)
    gemm(HR_H, HR_L, RD_H, RD_L, out, T, HIDDEN, MOE_INTER, 0);

    // ---- shared chain (accumulates into out) ----
    // idx5: BIG fused gate+up GEMM [T, 2*INTER]  <- ncu -s 5 -c 1 captures this
    gemm(XH, XL, SHGU_H, SHGU_L, GU, T, 2 * INTER, HIDDEN, 0);
    // idx6: shared swiglu
    {
        int n4 = T * INTER / 4;
        swiglu_split_kernel<<<(n4 + 255) / 256, 256>>>(GU, HSH_H, HSH_L, INTER / 4, n4);
    }
    // idx7: shared down-projection, accumulate into out
    gemm(HSH_H, HSH_L, SHD_H, SHD_L, out, T, HIDDEN, INTER, 1);
}